// round 3
// baseline (speedup 1.0000x reference)
#include <cuda_runtime.h>
#include <cuda_bf16.h>

// ---------------------------------------------------------------------------
// Child-Sum Tree-LSTM over a perfect binary tree. B=8, L=8192, D=768.
// Level-synchronous: 13 levels, parents M = 8*N  (N = 4096..1).
//
// Per parent m with children rows (2m, 2m+1) of the current level:
//   h_sum = h_l + h_r
//   iou   = (0.5*W_iou + U_iou) @ h_sum + b_iou          (gates 0..2: i,o,u)
//   wfx   = 0.5*W_f @ h_sum + b_f                        (gate 3)
//   ufs   = U_f @ h_sum                                  (gate 4)
//   ufl   = U_f @ h_l                                    (gate 5; A = h_l!)
//   f_l = sig(wfx+ufl); f_r = sig(wfx + ufs - ufl)
//   c = sig(i)*tanh(u) + f_l*c_l + f_r*c_r;  h = sig(o)*tanh(c)
//
// One fused GEMM per level, output N-dim = 6*D = 4608 columns permuted as
// n = j*6 + g so each thread owns all 6 gates of its (m, j) pairs and the
// LSTM epilogue fuses into the GEMM block. Inner loop uses packed
// fma.rn.f32x2 (2 FMA/inst; scalar 3-reg FFMA is half-rate on this SM).
// A is staged in smem interleaved as {h_sum, h_l} so the (ufs, ufl) gate
// pair consumes the mixed pair with a single LDS.64 and no packing movs.
// ---------------------------------------------------------------------------

#define TD   768
#define TG   6
#define TND  (TG*TD)      // 4608
#define TB   8
#define MAXM (TB*4096)    // max parents in a level = 32768
#define MAXMD (MAXM*TD)

// scratch (static device globals; allocation APIs are forbidden)
__device__ float g_hA[MAXMD];
__device__ float g_hB[MAXMD];
__device__ float g_cA[MAXMD];
__device__ float g_cB[MAXMD];
__device__ float g_Wt[TD * TND];   // Wt[k][n], n = j*6+g  (K-major weights)

typedef unsigned long long ull;
union F4U { float4 f4; ull u[2]; };
union F2U { float2 f2; ull u; };

__device__ __forceinline__ void ffma2(ull& d, ull a, ull b) {
    asm("fma.rn.f32x2 %0, %1, %2, %0;" : "+l"(d) : "l"(a), "l"(b));
}
__device__ __forceinline__ ull splat2(float x) {
    ull r;
    asm("mov.b64 %0, {%1, %1};" : "=l"(r) : "f"(x));
    return r;
}
__device__ __forceinline__ float sigm(float x) {
    return 1.0f / (1.0f + __expf(-x));
}

// ---------------------------------------------------------------------------
// Build permuted/fused weight matrix Wt[k][j*6+g]:
//  g=0..2 : 0.5*W_iou[g*D+j][k] + U_iou[g*D+j][k]   (i, o, u)
//  g=3    : 0.5*W_f[j][k]
//  g=4,5  : U_f[j][k]
// ---------------------------------------------------------------------------
__global__ void prep_w_kernel(const float* __restrict__ W_iou,
                              const float* __restrict__ U_iou,
                              const float* __restrict__ W_f,
                              const float* __restrict__ U_f) {
    int idx = blockIdx.x * blockDim.x + threadIdx.x;
    if (idx >= TD * TND) return;
    int k = idx / TND;
    int n = idx - k * TND;
    int j = n / TG;
    int g = n - j * TG;
    float v;
    if (g < 3) {
        int row = g * TD + j;
        v = 0.5f * W_iou[row * TD + k] + U_iou[row * TD + k];
    } else if (g == 3) {
        v = 0.5f * W_f[j * TD + k];
    } else {
        v = U_f[j * TD + k];
    }
    g_Wt[idx] = v;
}

// ---------------------------------------------------------------------------
// Fused GEMM + TreeLSTM epilogue.
// Tile: BM=128 (m) x BN=192 (32 j * 6 g), BK=16. 256 threads.
// Per-thread: 8 m x 12 n = 48 packed-f32x2 accumulators.
// h_sum is formed in-register during the A-tile load (no separate kernel).
// ---------------------------------------------------------------------------
#define BM 128
#define BN 192
#define BK 16
#define TM 8

struct Stage {
    float4 sl[2], sr[2];   // child rows l (2m) and r (2m+1), 2 m-reps
    float4 bq[3];          // weight tile fragment
};

__device__ __forceinline__ void stage_load(Stage& s, const float* __restrict__ hcur,
                                           int M, int m0, int n0,
                                           int ldm, int ldk, int ldk2, int ldn,
                                           int k0) {
#pragma unroll
    for (int rep = 0; rep < 2; ++rep) {
        int mm = ldm + rep * 64;
        int m  = m0 + mm;
        if (m < M) {
            const float* base = hcur + (size_t)(2 * m) * TD + k0 + ldk;
            s.sl[rep] = *(const float4*)(base);
            s.sr[rep] = *(const float4*)(base + TD);
        } else {
            s.sl[rep] = make_float4(0.f, 0.f, 0.f, 0.f);
            s.sr[rep] = make_float4(0.f, 0.f, 0.f, 0.f);
        }
    }
#pragma unroll
    for (int v = 0; v < 3; ++v)
        s.bq[v] = *(const float4*)(g_Wt + (size_t)(k0 + ldk2) * TND + n0 + ldn + v * 4);
}

__global__ __launch_bounds__(256, 1)
void tree_gemm_kernel(const float* __restrict__ leaf,
                      int src_sel, int dst_sel, float* __restrict__ dout,
                      const float* __restrict__ b_iou,
                      const float* __restrict__ b_f,
                      int M, int czero) {
    const float* hcur = (src_sel == 0) ? leaf : (src_sel == 1 ? g_hA : g_hB);
    const float* ccur = (src_sel == 1) ? g_cA : g_cB;   // unused when czero
    float* hout = (dst_sel == 3) ? dout            : (dst_sel == 1 ? g_hA : g_hB);
    float* cout = (dst_sel == 3) ? (dout + TB * TD) : (dst_sel == 1 ? g_cA : g_cB);

    __shared__ float2 Ap[BK][BM];   // {h_sum, h_l} interleaved
    __shared__ float  Bs[BK][BN];

    const int tid = threadIdx.x;
    const int tx = tid & 15;
    const int ty = tid >> 4;
    const int n0 = blockIdx.x * BN;     // n tile (j0 = n0/6)
    const int m0 = blockIdx.y * BM;     // m tile

    const int ldm  = tid >> 2;          // 0..63
    const int ldk  = (tid & 3) * 4;     // 0,4,8,12
    const int ldk2 = tid >> 4;          // 0..15
    const int ldn  = (tid & 15) * 12;   // 0..180

    ull acc[TM][6];
#pragma unroll
    for (int i = 0; i < TM; ++i)
#pragma unroll
        for (int n = 0; n < 6; ++n) acc[i][n] = 0ull;

    Stage st;
    stage_load(st, hcur, M, m0, n0, ldm, ldk, ldk2, ldn, 0);

    for (int k0 = 0; k0 < TD; k0 += BK) {
        // ---- commit staged tile to smem
#pragma unroll
        for (int rep = 0; rep < 2; ++rep) {
            int mm = ldm + rep * 64;
            float4 l = st.sl[rep], r = st.sr[rep];
            Ap[ldk + 0][mm] = make_float2(l.x + r.x, l.x);
            Ap[ldk + 1][mm] = make_float2(l.y + r.y, l.y);
            Ap[ldk + 2][mm] = make_float2(l.z + r.z, l.z);
            Ap[ldk + 3][mm] = make_float2(l.w + r.w, l.w);
        }
#pragma unroll
        for (int v = 0; v < 3; ++v)
            *(float4*)&Bs[ldk2][ldn + v * 4] = st.bq[v];
        __syncthreads();

        // ---- prefetch next tile (LDG latency overlaps compute below)
        if (k0 + BK < TD)
            stage_load(st, hcur, M, m0, n0, ldm, ldk, ldk2, ldn, k0 + BK);

        // ---- packed-f32x2 mainloop
#pragma unroll
        for (int kk = 0; kk < BK; ++kk) {
            F4U b0, b1, b2;
            b0.f4 = *(const float4*)&Bs[kk][tx * 12 + 0];
            b1.f4 = *(const float4*)&Bs[kk][tx * 12 + 4];
            b2.f4 = *(const float4*)&Bs[kk][tx * 12 + 8];
#pragma unroll
            for (int i = 0; i < TM; ++i) {
                F2U mx; mx.f2 = Ap[kk][ty * TM + i];  // {h_sum, h_l}
                ull aa = splat2(mx.f2.x);             // {h_sum, h_sum}
                ffma2(acc[i][0], aa,   b0.u[0]);  // jA (i, o)
                ffma2(acc[i][1], aa,   b0.u[1]);  // jA (u, wfx)
                ffma2(acc[i][2], mx.u, b1.u[0]);  // jA (ufs, ufl)
                ffma2(acc[i][3], aa,   b1.u[1]);  // jB (i, o)
                ffma2(acc[i][4], aa,   b2.u[0]);  // jB (u, wfx)
                ffma2(acc[i][5], mx.u, b2.u[1]);  // jB (ufs, ufl)
            }
        }
        __syncthreads();
    }

    // ---- fused TreeLSTM epilogue (float2-coalesced on the j pair) ----
    const int jA = n0 / TG + 2 * tx;    // thread owns columns jA, jA+1
    const float2 bi2 = *(const float2*)&b_iou[jA];
    const float2 bo2 = *(const float2*)&b_iou[TD + jA];
    const float2 bu2 = *(const float2*)&b_iou[2 * TD + jA];
    const float2 bf2 = *(const float2*)&b_f[jA];

#pragma unroll
    for (int i = 0; i < TM; ++i) {
        const int m = m0 + ty * TM + i;
        if (m >= M) continue;
        float2 cl2 = make_float2(0.f, 0.f), cr2 = make_float2(0.f, 0.f);
        if (!czero) {
            const float* cbase = ccur + (size_t)(2 * m) * TD + jA;
            cl2 = *(const float2*)(cbase);
            cr2 = *(const float2*)(cbase + TD);
        }
        F2U p0a, p1a, p2a, p0b, p1b, p2b;
        p0a.u = acc[i][0]; p1a.u = acc[i][1]; p2a.u = acc[i][2];
        p0b.u = acc[i][3]; p1b.u = acc[i][4]; p2b.u = acc[i][5];

        // column jA
        float ivA  = p0a.f2.x + bi2.x;
        float ovA  = p0a.f2.y + bo2.x;
        float uvA  = p1a.f2.x + bu2.x;
        float wfxA = p1a.f2.y + bf2.x;
        float flA = sigm(wfxA + p2a.f2.y);
        float frA = sigm(wfxA + (p2a.f2.x - p2a.f2.y));
        float cnA = sigm(ivA) * tanhf(uvA) + flA * cl2.x + frA * cr2.x;
        float hnA = sigm(ovA) * tanhf(cnA);

        // column jB = jA+1
        float ivB  = p0b.f2.x + bi2.y;
        float ovB  = p0b.f2.y + bo2.y;
        float uvB  = p1b.f2.x + bu2.y;
        float wfxB = p1b.f2.y + bf2.y;
        float flB = sigm(wfxB + p2b.f2.y);
        float frB = sigm(wfxB + (p2b.f2.x - p2b.f2.y));
        float cnB = sigm(ivB) * tanhf(uvB) + flB * cl2.y + frB * cr2.y;
        float hnB = sigm(ovB) * tanhf(cnB);

        *(float2*)(hout + (size_t)m * TD + jA) = make_float2(hnA, hnB);
        *(float2*)(cout + (size_t)m * TD + jA) = make_float2(cnA, cnB);
    }
}

// ---------------------------------------------------------------------------
extern "C" void kernel_launch(void* const* d_in, const int* in_sizes, int n_in,
                              void* d_out, int out_size) {
    const float* leaf  = (const float*)d_in[0];  // [8, 8192, 768]
    const float* W_iou = (const float*)d_in[1];  // [2304, 768]
    const float* b_iou = (const float*)d_in[2];  // [2304]
    const float* U_iou = (const float*)d_in[3];  // [2304, 768]
    const float* W_f   = (const float*)d_in[4];  // [768, 768]
    const float* b_f   = (const float*)d_in[5];  // [768]
    const float* U_f   = (const float*)d_in[6];  // [768, 768]
    float* out = (float*)d_out;                  // [2, 8, 768]

    // fuse + permute weights (cheap; rerun every call for determinism)
    {
        int tot = TD * TND;
        prep_w_kernel<<<(tot + 255) / 256, 256>>>(W_iou, U_iou, W_f, U_f);
    }

    int Np  = 4096;   // parents per batch item at level 0
    int src = 0;      // 0 = leaf input, 1 = A buffers, 2 = B buffers
    int dst = 1;
    for (int lvl = 0; lvl < 13; ++lvl) {
        const int M = TB * Np;                    // parents this level
        const int d = (lvl == 12) ? 3 : dst;
        dim3 grid(TND / BN, (M + BM - 1) / BM);   // (24, m-tiles)
        tree_gemm_kernel<<<grid, 256>>>(leaf, src, d, out, b_iou, b_f,
                                        M, lvl == 0 ? 1 : 0);
        src = dst;
        dst = (dst == 1) ? 2 : 1;
        Np >>= 1;
    }
}